// round 10
// baseline (speedup 1.0000x reference)
#include <cuda_runtime.h>

#define K          84
#define CHUNKS     21          // K/4 (16B chunks per row)
#define NPROTO     10
#define HALFP      5           // protos per warp-half
#define THREADS    256
#define STAGE_ROWS 256
#define STAGE_FLOATS (STAGE_ROWS * K)        // 21504
#define STAGE_BYTES  (STAGE_FLOATS * 4)      // 86016

// dynamic smem per CTA (1 CTA/SM):
//   buf[2][STAGE_FLOATS]   2*86016 B
//   wblk[210] ulonglong2   3360 B
//   w2[16] floats          64 B
//   mbar[2] u64            16 B (+pad)
#define SMEM_BYTES (2 * STAGE_BYTES + CHUNKS * NPROTO * 16 + 64 + 32)

__device__ __forceinline__ void ffma2(unsigned long long &d,
                                      unsigned long long a,
                                      unsigned long long b) {
    asm("fma.rn.f32x2 %0, %1, %2, %0;" : "+l"(d) : "l"(a), "l"(b));
}
__device__ __forceinline__ float f2lo(unsigned long long v) {
    return __int_as_float((unsigned)(v & 0xffffffffULL));
}
__device__ __forceinline__ float f2hi(unsigned long long v) {
    return __int_as_float((unsigned)(v >> 32));
}

__device__ __forceinline__ void mbar_init(unsigned mbar, unsigned count) {
    asm volatile("mbarrier.init.shared.b64 [%0], %1;" :: "r"(mbar), "r"(count) : "memory");
}
__device__ __forceinline__ void mbar_expect_tx(unsigned mbar, unsigned bytes) {
    asm volatile("mbarrier.arrive.expect_tx.shared.b64 _, [%0], %1;"
                 :: "r"(mbar), "r"(bytes) : "memory");
}
__device__ __forceinline__ void mbar_wait(unsigned mbar, unsigned parity) {
    unsigned done;
    asm volatile(
        "{\n\t"
        ".reg .pred p;\n\t"
        "mbarrier.try_wait.parity.acquire.cta.shared::cta.b64 p, [%1], %2;\n\t"
        "selp.b32 %0, 1, 0, p;\n\t"
        "}" : "=r"(done) : "r"(mbar), "r"(parity) : "memory");
    if (!done) {
        asm volatile(
            "{\n\t"
            ".reg .pred P1;\n\t"
            "WAIT_LOOP_%=:\n\t"
            "mbarrier.try_wait.parity.acquire.cta.shared::cta.b64 P1, [%0], %1, 0x989680;\n\t"
            "@P1 bra.uni WAIT_DONE_%=;\n\t"
            "bra.uni WAIT_LOOP_%=;\n\t"
            "WAIT_DONE_%=:\n\t"
            "}" :: "r"(mbar), "r"(parity) : "memory");
    }
}
__device__ __forceinline__ void bulk_g2s(unsigned dst_smem, const void* src,
                                         unsigned bytes, unsigned mbar) {
    asm volatile(
        "cp.async.bulk.shared::cta.global.mbarrier::complete_tx::bytes "
        "[%0], [%1], %2, [%3];"
        :: "r"(dst_smem), "l"(src), "r"(bytes), "r"(mbar) : "memory");
}

__global__ void __launch_bounds__(THREADS, 1)
rbf_kernel(const float* __restrict__ x,
           const float* __restrict__ weight,
           float* __restrict__ out,
           int nrows) {
    extern __shared__ __align__(16) float smem[];
    float* s_buf0 = smem;                                 // [STAGE_FLOATS]
    float* s_buf1 = smem + STAGE_FLOATS;                  // [STAGE_FLOATS]
    ulonglong2* s_w = (ulonglong2*)(smem + 2 * STAGE_FLOATS); // [210]
    float* s_w2 = (float*)(s_w + CHUNKS * NPROTO);        // [16]
    unsigned long long* s_mbar = (unsigned long long*)(s_w2 + 16); // [2]

    const int t    = threadIdx.x;
    const int tr   = t & (STAGE_ROWS / 2 - 1);   // 0..127: base row in stage
    const int half = t >> 7;                      // 0: protos 0-4, 1: protos 5-9
    const int k0   = half * HALFP;

    // ---- weight blocks: s_w[c*10+k] = chunk c of proto k ----
    for (int i = t; i < CHUNKS * NPROTO; i += THREADS) {
        int c = i / NPROTO;
        int k = i - c * NPROTO;
        const float4 v = *(const float4*)(weight + k * K + 4 * c);
        ulonglong2 u;
        u.x = ((unsigned long long)__float_as_uint(v.y) << 32) | __float_as_uint(v.x);
        u.y = ((unsigned long long)__float_as_uint(v.w) << 32) | __float_as_uint(v.z);
        s_w[i] = u;
    }
    if (t < NPROTO) {
        float s = 0.f;
        #pragma unroll
        for (int j = 0; j < K; j++) { float w = weight[t * K + j]; s += w * w; }
        s_w2[t] = s;
    }

    const unsigned mbar0 = (unsigned)__cvta_generic_to_shared(&s_mbar[0]);
    const unsigned mbar1 = (unsigned)__cvta_generic_to_shared(&s_mbar[1]);
    if (t == 0) { mbar_init(mbar0, 1); mbar_init(mbar1, 1); }

    unsigned buf_addr[2];
    buf_addr[0] = (unsigned)__cvta_generic_to_shared(s_buf0);
    buf_addr[1] = (unsigned)__cvta_generic_to_shared(s_buf1);
    const float* bufs[2] = { s_buf0, s_buf1 };
    const unsigned mbars[2] = { mbar0, mbar1 };

    const int nstages = (nrows + STAGE_ROWS - 1) / STAGE_ROWS;  // 2048
    const int step = gridDim.x;
    int count = 0;
    for (long long s = blockIdx.x; s < nstages; s += step) count++;

    __syncthreads();   // weights + mbarrier init visible

    auto issue_stage = [&](int j) {
        if (t == 0) {
            long long stage = (long long)blockIdx.x + (long long)j * step;
            long long row0 = stage * STAGE_ROWS;
            long long rem_rows = (long long)nrows - row0;
            unsigned bytes = (rem_rows >= STAGE_ROWS)
                           ? STAGE_BYTES
                           : (unsigned)(rem_rows * K * 4);
            mbar_expect_tx(mbars[j & 1], bytes);
            bulk_g2s(buf_addr[j & 1], x + row0 * K, bytes, mbars[j & 1]);
        }
    };

    if (count > 0) issue_stage(0);
    if (count > 1) issue_stage(1);

    for (int j = 0; j < count; j++) {
        mbar_wait(mbars[j & 1], (unsigned)((j >> 1) & 1));

        const long long stage = (long long)blockIdx.x + (long long)j * step;
        const float* sx = bufs[j & 1];

        const ulonglong2* rowA = (const ulonglong2*)(sx + tr * K);
        const ulonglong2* rowB = (const ulonglong2*)(sx + (tr + 128) * K);

        unsigned long long accA[HALFP], accB[HALFP];
        unsigned long long x2a = 0ULL, x2b = 0ULL;
        #pragma unroll
        for (int k = 0; k < HALFP; k++) { accA[k] = 0ULL; accB[k] = 0ULL; }

        #pragma unroll
        for (int c = 0; c < CHUNKS; c++) {
            ulonglong2 va = rowA[c];
            ulonglong2 vb = rowB[c];
            ffma2(x2a, va.x, va.x);
            ffma2(x2a, va.y, va.y);
            ffma2(x2b, vb.x, vb.x);
            ffma2(x2b, vb.y, vb.y);
            #pragma unroll
            for (int k = 0; k < HALFP; k++) {
                ulonglong2 wv = s_w[c * NPROTO + k0 + k];
                ffma2(accA[k], va.x, wv.x);
                ffma2(accA[k], va.y, wv.y);
                ffma2(accB[k], vb.x, wv.x);
                ffma2(accB[k], vb.y, wv.y);
            }
        }

        float x2A = f2lo(x2a) + f2hi(x2a);
        float x2B = f2lo(x2b) + f2hi(x2b);

        float resA[HALFP], resB[HALFP];
        #pragma unroll
        for (int k = 0; k < HALFP; k++) {
            float w2 = s_w2[k0 + k];
            resA[k] = fmaf(-2.f, f2lo(accA[k]) + f2hi(accA[k]), x2A + w2);
            resB[k] = fmaf(-2.f, f2lo(accB[k]) + f2hi(accB[k]), x2B + w2);
        }

        const long long rA = stage * STAGE_ROWS + tr;
        const long long rB = rA + 128;
        if (rA < nrows) {
            float* o = out + rA * NPROTO;
            if (half == 0) {
                *(float2*)(o + 0) = make_float2(resA[0], resA[1]);
                *(float2*)(o + 2) = make_float2(resA[2], resA[3]);
                o[4] = resA[4];
            } else {
                o[5] = resA[0];
                *(float2*)(o + 6) = make_float2(resA[1], resA[2]);
                *(float2*)(o + 8) = make_float2(resA[3], resA[4]);
            }
        }
        if (rB < nrows) {
            float* o = out + rB * NPROTO;
            if (half == 0) {
                *(float2*)(o + 0) = make_float2(resB[0], resB[1]);
                *(float2*)(o + 2) = make_float2(resB[2], resB[3]);
                o[4] = resB[4];
            } else {
                o[5] = resB[0];
                *(float2*)(o + 6) = make_float2(resB[1], resB[2]);
                *(float2*)(o + 8) = make_float2(resB[3], resB[4]);
            }
        }

        __syncthreads();                 // all warps done reading buffer j&1
        if (j + 2 < count) issue_stage(j + 2);
    }
}

extern "C" void kernel_launch(void* const* d_in, const int* in_sizes, int n_in,
                              void* d_out, int out_size) {
    const float* x = (const float*)d_in[0];
    const float* w = (const float*)d_in[1];
    float* out = (float*)d_out;

    const int nrows = in_sizes[0] / K;   // 524288

    static int nsm = 0;
    if (nsm == 0) {
        cudaFuncSetAttribute(rbf_kernel,
                             cudaFuncAttributeMaxDynamicSharedMemorySize,
                             SMEM_BYTES);
        cudaDeviceGetAttribute(&nsm, cudaDevAttrMultiProcessorCount, 0);
        if (nsm <= 0) nsm = 148;
    }

    // 1 CTA/SM, 8 warps: proto-split x row-pair halves weight LDS at full warp count
    rbf_kernel<<<nsm, THREADS, SMEM_BYTES>>>(x, w, out, nrows);
}